// round 11
// baseline (speedup 1.0000x reference)
#include <cuda_runtime.h>
#include <cuda_fp16.h>
#include <cstdint>

// SpiralConv gather-GEMM. R11: FP16 m16n8k16, BK=64 per stage (32 iters),
// swizzled 128B stage rows, 3-stage cp.async pipeline, 64x32 warp tiles.
// out[m,o] = relu(sum_k A[m,k]*W[o,k] + b[o]) * zp[m%N]; M=96000, K=2048, N=128.

constexpr int Bq = 8, Nq = 12000, Fq = 128, Sq = 16, OUTq = 128;
constexpr int Kq = Sq * Fq;       // 2048
constexpr int Mtot = Bq * Nq;     // 96000
constexpr int BM = 128;
constexpr int NITER = Kq / 64;    // 32 (BK=64)
constexpr int NST = 3;

// fp16 copies, per-32-group permuted: 16B slot s of each 32-elem group holds
// k = {2s,2s+1, 2s+8,2s+9, 2s+16,2s+17, 2s+24,2s+25}.
__device__ __half g_x[Bq * Nq * Fq];
__device__ __half g_w[OUTq * Kq];

// smem: stage rows are 128B (two 32-K groups); chunk pos swizzle
// pos(g,c,row) = (g ^ (row&1))*4 + (c ^ ((row>>1)&3)).
constexpr int STG = BM * 128;                       // 16384 per tile stage
constexpr int OFF_A = 0;                            // 3 stages
constexpr int OFF_B = OFF_A + NST * STG;            // 49152
constexpr int OFF_ATAB = OFF_B + NST * STG;         // 98304 (128*16 uint32)
constexpr int OFF_BIAS = OFF_ATAB + BM * Sq * 4;    // 106496
constexpr int SMEM_BYTES = OFF_BIAS + OUTq * 4;     // 107008

__device__ __forceinline__ void cp_async16(void* sdst, const void* gsrc) {
    unsigned d = (unsigned)__cvta_generic_to_shared(sdst);
    asm volatile("cp.async.cg.shared.global [%0], [%1], 16;" :: "r"(d), "l"(gsrc));
}

// ---- prepass: fp32 -> fp16 with per-32-group fragment permutation ----
__global__ void prep_kernel(const float* __restrict__ x, const float* __restrict__ W,
                            int xch, int totch) {
    int t = blockIdx.x * 256 + threadIdx.x;
    if (t >= totch) return;
    const float* src;
    __half* dst;
    int ch = t;
    if (t < xch) { src = x; dst = g_x; }
    else         { src = W; dst = g_w; ch = t - xch; }
    int gb = (ch >> 2) * 32 + (ch & 3) * 2;
    __half2 h0 = __float22half2_rn(*reinterpret_cast<const float2*>(src + gb));
    __half2 h1 = __float22half2_rn(*reinterpret_cast<const float2*>(src + gb + 8));
    __half2 h2 = __float22half2_rn(*reinterpret_cast<const float2*>(src + gb + 16));
    __half2 h3 = __float22half2_rn(*reinterpret_cast<const float2*>(src + gb + 24));
    uint4 v;
    v.x = *reinterpret_cast<uint32_t*>(&h0);
    v.y = *reinterpret_cast<uint32_t*>(&h1);
    v.z = *reinterpret_cast<uint32_t*>(&h2);
    v.w = *reinterpret_cast<uint32_t*>(&h3);
    reinterpret_cast<uint4*>(dst)[ch] = v;
}

extern __shared__ char smem[];

__global__ __launch_bounds__(256, 2) void spiral_mma_kernel(
    const float* __restrict__ bias,
    const int*   __restrict__ adj,
    const float* __restrict__ zp,
    float*       __restrict__ out)
{
    const int tid = threadIdx.x;
    const int m0 = blockIdx.x * BM;

    uint32_t* atab  = reinterpret_cast<uint32_t*>(smem + OFF_ATAB);
    float*    sbias = reinterpret_cast<float*>(smem + OFF_BIAS);

    // gather table: byte offset of fp16 x-row (256B each)
    for (int i = tid; i < BM * Sq; i += 256) {
        int r = i >> 4, s = i & 15;
        int mm = m0 + r;
        int b = mm / Nq, n = mm - b * Nq;
        atab[i] = (uint32_t)(b * Nq + adj[n * Sq + s]) << 8;
    }
    if (tid < OUTq) sbias[tid] = bias[tid];
    __syncthreads();

    // loader: thread owns row=tid&127, 64B half h=tid>>7; 4 chunks each A and B
    const int row = tid & 127;
    const int h   = tid >> 7;
    const int qq  = (row >> 1) & 3;
    const int pb  = (h ^ (row & 1)) << 2;           // stored group base
    const uint32_t* atp = atab + row * 16;
    int adst[4];
    #pragma unroll
    for (int j = 0; j < 4; ++j)
        adst[j] = row * 128 + ((pb + (j ^ qq)) << 4);
    const char* wrow = reinterpret_cast<const char*>(g_w) + row * (Kq * 2) + h * 64;

    auto load_stage = [&](int st, int it2) {
        const int sidx = it2 >> 1;                   // neighbor (128 K per neighbor)
        const char* gx = reinterpret_cast<const char*>(g_x)
                       + ((it2 & 1) << 7) + h * 64 + atp[sidx];
        const char* gw = wrow + (it2 << 7);
        char* abase = smem + OFF_A + st * STG;
        char* bbase = smem + OFF_B + st * STG;
        #pragma unroll
        for (int j = 0; j < 4; ++j)
            cp_async16(abase + adst[j], gx + j * 16);
        #pragma unroll
        for (int j = 0; j < 4; ++j)
            cp_async16(bbase + adst[j], gw + j * 16);
    };

    load_stage(0, 0); asm volatile("cp.async.commit_group;");
    load_stage(1, 1); asm volatile("cp.async.commit_group;");

    const int lane = tid & 31;
    const int warp = tid >> 5;
    const int wm = (warp & 1) * 64;   // 2 warps over M
    const int wn = (warp >> 1) * 32;  // 4 warps over N
    const int tr = lane >> 2;         // 0..7
    const int tc = lane & 3;          // 0..3
    const int par = tr & 1;
    const int q2  = tr >> 1;          // 0..3
    const int chn0 = ((0 ^ par) << 2) + (tc ^ q2);   // group 0 chunk pos
    const int chn1 = ((1 ^ par) << 2) + (tc ^ q2);   // group 1 chunk pos

    float acc[4][4][4];
    #pragma unroll
    for (int a = 0; a < 4; ++a)
        #pragma unroll
        for (int b2 = 0; b2 < 4; ++b2)
            #pragma unroll
            for (int c = 0; c < 4; ++c) acc[a][b2][c] = 0.f;

    int cur = 0, nx2 = 2;
    #pragma unroll 1
    for (int it = 0; it < NITER; ++it) {
        asm volatile("cp.async.wait_group 1;");
        __syncthreads();
        if (it + 2 < NITER) load_stage(nx2, it + 2);
        asm volatile("cp.async.commit_group;");

        const uint4* A4 = reinterpret_cast<const uint4*>(smem + OFF_A + cur * STG);
        const uint4* B4 = reinterpret_cast<const uint4*>(smem + OFF_B + cur * STG);

        #pragma unroll
        for (int g = 0; g < 2; ++g) {
            const int chn = g ? chn1 : chn0;
            uint4 bfr[4];
            #pragma unroll
            for (int nt = 0; nt < 4; ++nt)
                bfr[nt] = B4[(wn + nt * 8 + tr) * 8 + chn];
            #pragma unroll
            for (int mt = 0; mt < 4; ++mt) {
                const int r = wm + mt * 16 + tr;
                uint4 alo = A4[r * 8 + chn];
                uint4 ahi = A4[(r + 8) * 8 + chn];
                #pragma unroll
                for (int nt = 0; nt < 4; ++nt)
                    asm volatile(
                        "mma.sync.aligned.m16n8k16.row.col.f32.f16.f16.f32 "
                        "{%0,%1,%2,%3}, {%4,%5,%6,%7}, {%8,%9}, {%0,%1,%2,%3};"
                        : "+f"(acc[mt][nt][0]), "+f"(acc[mt][nt][1]),
                          "+f"(acc[mt][nt][2]), "+f"(acc[mt][nt][3])
                        : "r"(alo.x), "r"(ahi.x), "r"(alo.y), "r"(ahi.y),
                          "r"(bfr[nt].x), "r"(bfr[nt].y));
                #pragma unroll
                for (int nt = 0; nt < 4; ++nt)
                    asm volatile(
                        "mma.sync.aligned.m16n8k16.row.col.f32.f16.f16.f32 "
                        "{%0,%1,%2,%3}, {%4,%5,%6,%7}, {%8,%9}, {%0,%1,%2,%3};"
                        : "+f"(acc[mt][nt][0]), "+f"(acc[mt][nt][1]),
                          "+f"(acc[mt][nt][2]), "+f"(acc[mt][nt][3])
                        : "r"(alo.z), "r"(ahi.z), "r"(alo.w), "r"(ahi.w),
                          "r"(bfr[nt].z), "r"(bfr[nt].w));
            }
        }

        cur = (cur == NST - 1) ? 0 : cur + 1;
        nx2 = (nx2 == NST - 1) ? 0 : nx2 + 1;
    }

    // ---- epilogue: bias + relu + zero_padding ----
    #pragma unroll
    for (int mt = 0; mt < 4; ++mt) {
        #pragma unroll
        for (int hh = 0; hh < 2; ++hh) {
            int m = m0 + wm + mt * 16 + hh * 8 + tr;
            float z = zp[m % Nq];
            float* orow = out + (long)m * OUTq;
            #pragma unroll
            for (int nt = 0; nt < 4; ++nt) {
                int o = wn + nt * 8 + 2 * tc;
                float v0 = fmaxf(acc[mt][nt][hh * 2 + 0] + sbias[o], 0.f) * z;
                float v1 = fmaxf(acc[mt][nt][hh * 2 + 1] + sbias[o + 1], 0.f) * z;
                *reinterpret_cast<float2*>(orow + o) = make_float2(v0, v1);
            }
        }
    }
}

extern "C" void kernel_launch(void* const* d_in, const int* in_sizes, int n_in,
                              void* d_out, int out_size) {
    const float* x    = (const float*)d_in[0];
    const float* W    = (const float*)d_in[1];
    const float* bias = (const float*)d_in[2];
    const int*   adj  = (const int*)d_in[3];
    const float* zp   = (const float*)d_in[4];
    float* out = (float*)d_out;

    int xch = (Bq * Nq * Fq) / 8;            // 1,536,000 16B chunks
    int totch = xch + (OUTq * Kq) / 8;       // + 32,768
    prep_kernel<<<(totch + 255) / 256, 256>>>(x, W, xch, totch);

    cudaFuncSetAttribute(spiral_mma_kernel,
                         cudaFuncAttributeMaxDynamicSharedMemorySize, SMEM_BYTES);
    spiral_mma_kernel<<<Mtot / BM, 256, SMEM_BYTES>>>(bias, adj, zp, out);
}

// round 12
// speedup vs baseline: 1.8739x; 1.8739x over previous
#include <cuda_runtime.h>
#include <cuda_fp16.h>
#include <cstdint>

// SpiralConv gather-GEMM. R12: FP16 m16n8k16, BK=64 (32 iters), 3-stage
// cp.async pipeline, coalesced loader (8 lanes per 128B row), swizzled rows.
// out[m,o] = relu(sum_k A[m,k]*W[o,k] + b[o]) * zp[m%N]; M=96000, K=2048, N=128.

constexpr int Bq = 8, Nq = 12000, Fq = 128, Sq = 16, OUTq = 128;
constexpr int Kq = Sq * Fq;       // 2048
constexpr int Mtot = Bq * Nq;     // 96000
constexpr int BM = 128;
constexpr int NITER = Kq / 64;    // 32 (BK=64)
constexpr int NST = 3;

// fp16 copies, per-32-group permuted: 16B slot s of each 32-elem group holds
// k = {2s,2s+1, 2s+8,2s+9, 2s+16,2s+17, 2s+24,2s+25}.
__device__ __half g_x[Bq * Nq * Fq];
__device__ __half g_w[OUTq * Kq];

// smem: stage rows are 128B (two 32-K groups); chunk pos swizzle
// pos(g,c,row) = ((g ^ (row&1))<<2) + (c ^ ((row>>1)&3)).
constexpr int STG = BM * 128;                       // 16384 per tile stage
constexpr int OFF_A = 0;                            // 3 stages
constexpr int OFF_B = OFF_A + NST * STG;            // 49152
constexpr int OFF_ATAB = OFF_B + NST * STG;         // 98304 (128*16 uint32)
constexpr int OFF_BIAS = OFF_ATAB + BM * Sq * 4;    // 106496
constexpr int SMEM_BYTES = OFF_BIAS + OUTq * 4;     // 107008

__device__ __forceinline__ void cp_async16(void* sdst, const void* gsrc) {
    unsigned d = (unsigned)__cvta_generic_to_shared(sdst);
    asm volatile("cp.async.cg.shared.global [%0], [%1], 16;" :: "r"(d), "l"(gsrc));
}

// ---- prepass: fp32 -> fp16 with per-32-group fragment permutation ----
__global__ void prep_kernel(const float* __restrict__ x, const float* __restrict__ W,
                            int xch, int totch) {
    int t = blockIdx.x * 256 + threadIdx.x;
    if (t >= totch) return;
    const float* src;
    __half* dst;
    int ch = t;
    if (t < xch) { src = x; dst = g_x; }
    else         { src = W; dst = g_w; ch = t - xch; }
    int gb = (ch >> 2) * 32 + (ch & 3) * 2;
    __half2 h0 = __float22half2_rn(*reinterpret_cast<const float2*>(src + gb));
    __half2 h1 = __float22half2_rn(*reinterpret_cast<const float2*>(src + gb + 8));
    __half2 h2 = __float22half2_rn(*reinterpret_cast<const float2*>(src + gb + 16));
    __half2 h3 = __float22half2_rn(*reinterpret_cast<const float2*>(src + gb + 24));
    uint4 v;
    v.x = *reinterpret_cast<uint32_t*>(&h0);
    v.y = *reinterpret_cast<uint32_t*>(&h1);
    v.z = *reinterpret_cast<uint32_t*>(&h2);
    v.w = *reinterpret_cast<uint32_t*>(&h3);
    reinterpret_cast<uint4*>(dst)[ch] = v;
}

extern __shared__ char smem[];

__global__ __launch_bounds__(256, 2) void spiral_mma_kernel(
    const float* __restrict__ bias,
    const int*   __restrict__ adj,
    const float* __restrict__ zp,
    float*       __restrict__ out)
{
    const int tid = threadIdx.x;
    const int m0 = blockIdx.x * BM;

    uint32_t* atab  = reinterpret_cast<uint32_t*>(smem + OFF_ATAB);
    float*    sbias = reinterpret_cast<float*>(smem + OFF_BIAS);

    // gather table: byte offset of fp16 x-row (256B each)
    for (int i = tid; i < BM * Sq; i += 256) {
        int r = i >> 4, s = i & 15;
        int mm = m0 + r;
        int b = mm / Nq, n = mm - b * Nq;
        atab[i] = (uint32_t)(b * Nq + adj[n * Sq + s]) << 8;
    }
    if (tid < OUTq) sbias[tid] = bias[tid];
    __syncthreads();

    // loader: 8 lanes cover one row's 128B; rows lr+32j (j=0..3)
    const int lr = tid >> 3;          // 0..31
    const int lc = tid & 7;           // 16B chunk 0..7
    const int g  = lc >> 2;           // source group within 128B
    const int c  = lc & 3;            // slot within group
    const uint32_t* atp = atab + lr * 16;   // row lr+32j -> atp[512*j + sidx]
    int adst[4];
    const char* wsrc[4];
    #pragma unroll
    for (int j = 0; j < 4; ++j) {
        int row = lr + j * 32;
        int pos = ((g ^ (row & 1)) << 2) + (c ^ ((row >> 1) & 3));
        adst[j] = row * 128 + (pos << 4);
        wsrc[j] = reinterpret_cast<const char*>(g_w) + row * (Kq * 2) + lc * 16;
    }

    auto load_stage = [&](int st, int it2) {
        const int sidx = it2 >> 1;                  // neighbor (256B per neighbor)
        const char* gx = reinterpret_cast<const char*>(g_x)
                       + ((it2 & 1) << 7) + lc * 16;
        const int wadv = it2 << 7;                  // 128B of W per iter
        char* abase = smem + OFF_A + st * STG;
        char* bbase = smem + OFF_B + st * STG;
        #pragma unroll
        for (int j = 0; j < 4; ++j)
            cp_async16(abase + adst[j], gx + atp[512 * j + sidx]);
        #pragma unroll
        for (int j = 0; j < 4; ++j)
            cp_async16(bbase + adst[j], wsrc[j] + wadv);
    };

    load_stage(0, 0); asm volatile("cp.async.commit_group;");
    load_stage(1, 1); asm volatile("cp.async.commit_group;");

    const int lane = tid & 31;
    const int warp = tid >> 5;
    const int wm = (warp & 1) * 64;   // 2 warps over M
    const int wn = (warp >> 1) * 32;  // 4 warps over N
    const int tr = lane >> 2;         // 0..7
    const int tc = lane & 3;          // 0..3
    const int par = tr & 1;
    const int q2  = tr >> 1;
    const int chn0 = ((0 ^ par) << 2) + (tc ^ q2);
    const int chn1 = ((1 ^ par) << 2) + (tc ^ q2);

    float acc[4][4][4];
    #pragma unroll
    for (int a = 0; a < 4; ++a)
        #pragma unroll
        for (int b2 = 0; b2 < 4; ++b2)
            #pragma unroll
            for (int cc = 0; cc < 4; ++cc) acc[a][b2][cc] = 0.f;

    int cur = 0, nx2 = 2;
    #pragma unroll 1
    for (int it = 0; it < NITER; ++it) {
        asm volatile("cp.async.wait_group 1;");
        __syncthreads();
        if (it + 2 < NITER) load_stage(nx2, it + 2);
        asm volatile("cp.async.commit_group;");

        const uint4* A4 = reinterpret_cast<const uint4*>(smem + OFF_A + cur * STG);
        const uint4* B4 = reinterpret_cast<const uint4*>(smem + OFF_B + cur * STG);

        #pragma unroll
        for (int gg = 0; gg < 2; ++gg) {
            const int chn = gg ? chn1 : chn0;
            uint4 bfr[4];
            #pragma unroll
            for (int nt = 0; nt < 4; ++nt)
                bfr[nt] = B4[(wn + nt * 8 + tr) * 8 + chn];
            #pragma unroll
            for (int mt = 0; mt < 4; ++mt) {
                const int r = wm + mt * 16 + tr;
                uint4 alo = A4[r * 8 + chn];
                uint4 ahi = A4[(r + 8) * 8 + chn];
                #pragma unroll
                for (int nt = 0; nt < 4; ++nt)
                    asm volatile(
                        "mma.sync.aligned.m16n8k16.row.col.f32.f16.f16.f32 "
                        "{%0,%1,%2,%3}, {%4,%5,%6,%7}, {%8,%9}, {%0,%1,%2,%3};"
                        : "+f"(acc[mt][nt][0]), "+f"(acc[mt][nt][1]),
                          "+f"(acc[mt][nt][2]), "+f"(acc[mt][nt][3])
                        : "r"(alo.x), "r"(ahi.x), "r"(alo.y), "r"(ahi.y),
                          "r"(bfr[nt].x), "r"(bfr[nt].y));
                #pragma unroll
                for (int nt = 0; nt < 4; ++nt)
                    asm volatile(
                        "mma.sync.aligned.m16n8k16.row.col.f32.f16.f16.f32 "
                        "{%0,%1,%2,%3}, {%4,%5,%6,%7}, {%8,%9}, {%0,%1,%2,%3};"
                        : "+f"(acc[mt][nt][0]), "+f"(acc[mt][nt][1]),
                          "+f"(acc[mt][nt][2]), "+f"(acc[mt][nt][3])
                        : "r"(alo.z), "r"(ahi.z), "r"(alo.w), "r"(ahi.w),
                          "r"(bfr[nt].z), "r"(bfr[nt].w));
            }
        }

        cur = (cur == NST - 1) ? 0 : cur + 1;
        nx2 = (nx2 == NST - 1) ? 0 : nx2 + 1;
    }

    // ---- epilogue: bias + relu + zero_padding ----
    #pragma unroll
    for (int mt = 0; mt < 4; ++mt) {
        #pragma unroll
        for (int hh = 0; hh < 2; ++hh) {
            int m = m0 + wm + mt * 16 + hh * 8 + tr;
            float z = zp[m % Nq];
            float* orow = out + (long)m * OUTq;
            #pragma unroll
            for (int nt = 0; nt < 4; ++nt) {
                int o = wn + nt * 8 + 2 * tc;
                float v0 = fmaxf(acc[mt][nt][hh * 2 + 0] + sbias[o], 0.f) * z;
                float v1 = fmaxf(acc[mt][nt][hh * 2 + 1] + sbias[o + 1], 0.f) * z;
                *reinterpret_cast<float2*>(orow + o) = make_float2(v0, v1);
            }
        }
    }
}

extern "C" void kernel_launch(void* const* d_in, const int* in_sizes, int n_in,
                              void* d_out, int out_size) {
    const float* x    = (const float*)d_in[0];
    const float* W    = (const float*)d_in[1];
    const float* bias = (const float*)d_in[2];
    const int*   adj  = (const int*)d_in[3];
    const float* zp   = (const float*)d_in[4];
    float* out = (float*)d_out;

    int xch = (Bq * Nq * Fq) / 8;            // 1,536,000 16B chunks
    int totch = xch + (OUTq * Kq) / 8;       // + 32,768
    prep_kernel<<<(totch + 255) / 256, 256>>>(x, W, xch, totch);

    cudaFuncSetAttribute(spiral_mma_kernel,
                         cudaFuncAttributeMaxDynamicSharedMemorySize, SMEM_BYTES);
    spiral_mma_kernel<<<Mtot / BM, 256, SMEM_BYTES>>>(bias, adj, zp, out);
}

// round 13
// speedup vs baseline: 1.9072x; 1.0177x over previous
#include <cuda_runtime.h>
#include <cuda_fp16.h>
#include <cstdint>

// SpiralConv gather-GEMM. R13 = R12 (FP16 m16n8k16, BK=64, coalesced loader,
// swizzled rows) + mbarrier free-run pipeline (no __syncthreads in mainloop).
// out[m,o] = relu(sum_k A[m,k]*W[o,k] + b[o]) * zp[m%N]; M=96000, K=2048, N=128.

constexpr int Bq = 8, Nq = 12000, Fq = 128, Sq = 16, OUTq = 128;
constexpr int Kq = Sq * Fq;       // 2048
constexpr int Mtot = Bq * Nq;     // 96000
constexpr int BM = 128;
constexpr int NITER = Kq / 64;    // 32 (BK=64)
constexpr int NST = 3;

// fp16 copies, per-32-group permuted: 16B slot s of each 32-elem group holds
// k = {2s,2s+1, 2s+8,2s+9, 2s+16,2s+17, 2s+24,2s+25}.
__device__ __half g_x[Bq * Nq * Fq];
__device__ __half g_w[OUTq * Kq];

// smem: stage rows are 128B; chunk pos swizzle
// pos(g,c,row) = ((g ^ (row&1))<<2) + (c ^ ((row>>1)&3)).
constexpr int STG = BM * 128;                       // 16384 per tile stage
constexpr int OFF_A = 0;                            // 3 stages
constexpr int OFF_B = OFF_A + NST * STG;            // 49152
constexpr int OFF_ATAB = OFF_B + NST * STG;         // 98304 (128*16 uint32)
constexpr int OFF_BIAS = OFF_ATAB + BM * Sq * 4;    // 106496
constexpr int OFF_MBAR = OFF_BIAS + OUTq * 4;       // 107008 (3 x {full,empty})
constexpr int SMEM_BYTES = OFF_MBAR + NST * 16;     // 107056

__device__ __forceinline__ void cp_async16(void* sdst, const void* gsrc) {
    unsigned d = (unsigned)__cvta_generic_to_shared(sdst);
    asm volatile("cp.async.cg.shared.global [%0], [%1], 16;" :: "r"(d), "l"(gsrc));
}

__device__ __forceinline__ void mbar_init(uint32_t a, uint32_t cnt) {
    asm volatile("mbarrier.init.shared.b64 [%0], %1;" :: "r"(a), "r"(cnt) : "memory");
}

__device__ __forceinline__ void mbar_arrive(uint32_t a) {
    asm volatile("mbarrier.arrive.shared::cta.b64 _, [%0];" :: "r"(a) : "memory");
}

__device__ __forceinline__ void cpasync_mbar_arrive_noinc(uint32_t a) {
    asm volatile("cp.async.mbarrier.arrive.noinc.shared::cta.b64 [%0];" :: "r"(a) : "memory");
}

__device__ __forceinline__ void mbar_wait(uint32_t a, uint32_t parity) {
    uint32_t done;
    asm volatile("{\n\t.reg .pred p;\n\t"
                 "mbarrier.try_wait.parity.acquire.cta.shared::cta.b64 p, [%1], %2;\n\t"
                 "selp.b32 %0, 1, 0, p;\n\t}"
                 : "=r"(done) : "r"(a), "r"(parity) : "memory");
    if (!done) {
        asm volatile("{\n\t.reg .pred P1;\n\t"
                     "W_%=:\n\t"
                     "mbarrier.try_wait.parity.acquire.cta.shared::cta.b64 P1, [%0], %1, 0x989680;\n\t"
                     "@P1 bra.uni D_%=;\n\t"
                     "bra.uni W_%=;\n\t"
                     "D_%=:\n\t}"
                     :: "r"(a), "r"(parity) : "memory");
    }
}

// ---- prepass: fp32 -> fp16 with per-32-group fragment permutation ----
__global__ void prep_kernel(const float* __restrict__ x, const float* __restrict__ W,
                            int xch, int totch) {
    int t = blockIdx.x * 256 + threadIdx.x;
    if (t >= totch) return;
    const float* src;
    __half* dst;
    int ch = t;
    if (t < xch) { src = x; dst = g_x; }
    else         { src = W; dst = g_w; ch = t - xch; }
    int gb = (ch >> 2) * 32 + (ch & 3) * 2;
    __half2 h0 = __float22half2_rn(*reinterpret_cast<const float2*>(src + gb));
    __half2 h1 = __float22half2_rn(*reinterpret_cast<const float2*>(src + gb + 8));
    __half2 h2 = __float22half2_rn(*reinterpret_cast<const float2*>(src + gb + 16));
    __half2 h3 = __float22half2_rn(*reinterpret_cast<const float2*>(src + gb + 24));
    uint4 v;
    v.x = *reinterpret_cast<uint32_t*>(&h0);
    v.y = *reinterpret_cast<uint32_t*>(&h1);
    v.z = *reinterpret_cast<uint32_t*>(&h2);
    v.w = *reinterpret_cast<uint32_t*>(&h3);
    reinterpret_cast<uint4*>(dst)[ch] = v;
}

extern __shared__ char smem[];

__global__ __launch_bounds__(256, 2) void spiral_mma_kernel(
    const float* __restrict__ bias,
    const int*   __restrict__ adj,
    const float* __restrict__ zp,
    float*       __restrict__ out)
{
    const int tid = threadIdx.x;
    const int m0 = blockIdx.x * BM;
    uint32_t sb;
    asm("{ .reg .u64 t; cvta.to.shared.u64 t, %1; cvt.u32.u64 %0, t; }"
        : "=r"(sb) : "l"(smem));

    uint32_t* atab  = reinterpret_cast<uint32_t*>(smem + OFF_ATAB);
    float*    sbias = reinterpret_cast<float*>(smem + OFF_BIAS);

    // gather table: byte offset of fp16 x-row (256B each)
    for (int i = tid; i < BM * Sq; i += 256) {
        int r = i >> 4, s = i & 15;
        int mm = m0 + r;
        int b = mm / Nq, n = mm - b * Nq;
        atab[i] = (uint32_t)(b * Nq + adj[n * Sq + s]) << 8;
    }
    if (tid < OUTq) sbias[tid] = bias[tid];
    if (tid == 0) {
        #pragma unroll
        for (int s = 0; s < NST; ++s) {
            mbar_init(sb + OFF_MBAR + s * 16, 256);      // full[s]
            mbar_init(sb + OFF_MBAR + s * 16 + 8, 256);  // empty[s]
        }
    }
    __syncthreads();

    // loader: 8 lanes cover one row's 128B; rows lr+32j (j=0..3)
    const int lr = tid >> 3;          // 0..31
    const int lc = tid & 7;           // 16B chunk 0..7
    const int g  = lc >> 2;
    const int c  = lc & 3;
    const uint32_t* atp = atab + lr * 16;   // row lr+32j -> atp[512*j + sidx]
    int adst[4];
    const char* wsrc[4];
    #pragma unroll
    for (int j = 0; j < 4; ++j) {
        int row = lr + j * 32;
        int pos = ((g ^ (row & 1)) << 2) + (c ^ ((row >> 1) & 3));
        adst[j] = row * 128 + (pos << 4);
        wsrc[j] = reinterpret_cast<const char*>(g_w) + row * (Kq * 2) + lc * 16;
    }

    auto produce = [&](int st, int parity, int it2) {
        mbar_wait(sb + OFF_MBAR + st * 16 + 8, parity);      // empty[st]
        const int sidx = it2 >> 1;
        const char* gx = reinterpret_cast<const char*>(g_x)
                       + ((it2 & 1) << 7) + lc * 16;
        const int wadv = it2 << 7;
        char* abase = smem + OFF_A + st * STG;
        char* bbase = smem + OFF_B + st * STG;
        #pragma unroll
        for (int j = 0; j < 4; ++j)
            cp_async16(abase + adst[j], gx + atp[512 * j + sidx]);
        #pragma unroll
        for (int j = 0; j < 4; ++j)
            cp_async16(bbase + adst[j], wsrc[j] + wadv);
        cpasync_mbar_arrive_noinc(sb + OFF_MBAR + st * 16);  // full[st]
    };

    const int lane = tid & 31;
    const int warp = tid >> 5;
    const int wm = (warp & 1) * 64;   // 2 warps over M
    const int wn = (warp >> 1) * 32;  // 4 warps over N
    const int tr = lane >> 2;
    const int tc = lane & 3;
    const int par = tr & 1;
    const int q2  = tr >> 1;
    const int chn0 = ((0 ^ par) << 2) + (tc ^ q2);
    const int chn1 = ((1 ^ par) << 2) + (tc ^ q2);

    float acc[4][4][4];
    #pragma unroll
    for (int a = 0; a < 4; ++a)
        #pragma unroll
        for (int b2 = 0; b2 < 4; ++b2)
            #pragma unroll
            for (int cc = 0; cc < 4; ++cc) acc[a][b2][cc] = 0.f;

    auto consume = [&](int st, int parity) {
        mbar_wait(sb + OFF_MBAR + st * 16, parity);          // full[st]
        const uint4* A4 = reinterpret_cast<const uint4*>(smem + OFF_A + st * STG);
        const uint4* B4 = reinterpret_cast<const uint4*>(smem + OFF_B + st * STG);
        #pragma unroll
        for (int gg = 0; gg < 2; ++gg) {
            const int chn = gg ? chn1 : chn0;
            uint4 bfr[4];
            #pragma unroll
            for (int nt = 0; nt < 4; ++nt)
                bfr[nt] = B4[(wn + nt * 8 + tr) * 8 + chn];
            #pragma unroll
            for (int mt = 0; mt < 4; ++mt) {
                const int r = wm + mt * 16 + tr;
                uint4 alo = A4[r * 8 + chn];
                uint4 ahi = A4[(r + 8) * 8 + chn];
                #pragma unroll
                for (int nt = 0; nt < 4; ++nt)
                    asm volatile(
                        "mma.sync.aligned.m16n8k16.row.col.f32.f16.f16.f32 "
                        "{%0,%1,%2,%3}, {%4,%5,%6,%7}, {%8,%9}, {%0,%1,%2,%3};"
                        : "+f"(acc[mt][nt][0]), "+f"(acc[mt][nt][1]),
                          "+f"(acc[mt][nt][2]), "+f"(acc[mt][nt][3])
                        : "r"(alo.x), "r"(ahi.x), "r"(alo.y), "r"(ahi.y),
                          "r"(bfr[nt].x), "r"(bfr[nt].y));
                #pragma unroll
                for (int nt = 0; nt < 4; ++nt)
                    asm volatile(
                        "mma.sync.aligned.m16n8k16.row.col.f32.f16.f16.f32 "
                        "{%0,%1,%2,%3}, {%4,%5,%6,%7}, {%8,%9}, {%0,%1,%2,%3};"
                        : "+f"(acc[mt][nt][0]), "+f"(acc[mt][nt][1]),
                          "+f"(acc[mt][nt][2]), "+f"(acc[mt][nt][3])
                        : "r"(alo.z), "r"(ahi.z), "r"(alo.w), "r"(ahi.w),
                          "r"(bfr[nt].z), "r"(bfr[nt].w));
            }
        }
        mbar_arrive(sb + OFF_MBAR + st * 16 + 8);            // empty[st]
    };

    // prologue (fresh-barrier empty-waits pass with parity 1)
    produce(0, 1, 0);
    produce(1, 1, 1);

    int ps = 2, pp = 1;
    int cs = 0, cp = 0;
    #pragma unroll 1
    for (int it = 0; it < NITER; ++it) {
        if (it + 2 < NITER) {
            produce(ps, pp, it + 2);
            if (++ps == NST) { ps = 0; pp ^= 1; }
        }
        consume(cs, cp);
        if (++cs == NST) { cs = 0; cp ^= 1; }
    }

    // ---- epilogue: bias + relu + zero_padding ----
    #pragma unroll
    for (int mt = 0; mt < 4; ++mt) {
        #pragma unroll
        for (int hh = 0; hh < 2; ++hh) {
            int m = m0 + wm + mt * 16 + hh * 8 + tr;
            float z = zp[m % Nq];
            float* orow = out + (long)m * OUTq;
            #pragma unroll
            for (int nt = 0; nt < 4; ++nt) {
                int o = wn + nt * 8 + 2 * tc;
                float v0 = fmaxf(acc[mt][nt][hh * 2 + 0] + sbias[o], 0.f) * z;
                float v1 = fmaxf(acc[mt][nt][hh * 2 + 1] + sbias[o + 1], 0.f) * z;
                *reinterpret_cast<float2*>(orow + o) = make_float2(v0, v1);
            }
        }
    }
}

extern "C" void kernel_launch(void* const* d_in, const int* in_sizes, int n_in,
                              void* d_out, int out_size) {
    const float* x    = (const float*)d_in[0];
    const float* W    = (const float*)d_in[1];
    const float* bias = (const float*)d_in[2];
    const int*   adj  = (const int*)d_in[3];
    const float* zp   = (const float*)d_in[4];
    float* out = (float*)d_out;

    int xch = (Bq * Nq * Fq) / 8;            // 1,536,000 16B chunks
    int totch = xch + (OUTq * Kq) / 8;       // + 32,768
    prep_kernel<<<(totch + 255) / 256, 256>>>(x, W, xch, totch);

    cudaFuncSetAttribute(spiral_mma_kernel,
                         cudaFuncAttributeMaxDynamicSharedMemorySize, SMEM_BYTES);
    spiral_mma_kernel<<<Mtot / BM, 256, SMEM_BYTES>>>(bias, adj, zp, out);
}

// round 14
// speedup vs baseline: 1.9809x; 1.0386x over previous
#include <cuda_runtime.h>
#include <cuda_fp16.h>
#include <cstdint>

// SpiralConv gather-GEMM. R14 = R13 (FP16 m16n8k16, BK=64, mbar free-run) +
// immediate-offset fragment LDS (4 base regs), produce interleaved mid-iter,
// relaxed producer wait.
// out[m,o] = relu(sum_k A[m,k]*W[o,k] + b[o]) * zp[m%N]; M=96000, K=2048, N=128.

constexpr int Bq = 8, Nq = 12000, Fq = 128, Sq = 16, OUTq = 128;
constexpr int Kq = Sq * Fq;       // 2048
constexpr int Mtot = Bq * Nq;     // 96000
constexpr int BM = 128;
constexpr int NITER = Kq / 64;    // 32 (BK=64)
constexpr int NST = 3;

__device__ __half g_x[Bq * Nq * Fq];
__device__ __half g_w[OUTq * Kq];

constexpr int STG = BM * 128;                       // 16384 per tile stage
constexpr int OFF_A = 0;
constexpr int OFF_B = OFF_A + NST * STG;            // 49152
constexpr int OFF_ATAB = OFF_B + NST * STG;         // 98304
constexpr int OFF_BIAS = OFF_ATAB + BM * Sq * 4;    // 106496
constexpr int OFF_MBAR = OFF_BIAS + OUTq * 4;       // 107008
constexpr int SMEM_BYTES = OFF_MBAR + NST * 16;     // 107056

__device__ __forceinline__ void cp_async16(void* sdst, const void* gsrc) {
    unsigned d = (unsigned)__cvta_generic_to_shared(sdst);
    asm volatile("cp.async.cg.shared.global [%0], [%1], 16;" :: "r"(d), "l"(gsrc));
}

__device__ __forceinline__ void mbar_init(uint32_t a, uint32_t cnt) {
    asm volatile("mbarrier.init.shared.b64 [%0], %1;" :: "r"(a), "r"(cnt) : "memory");
}
__device__ __forceinline__ void mbar_arrive(uint32_t a) {
    asm volatile("mbarrier.arrive.shared::cta.b64 _, [%0];" :: "r"(a) : "memory");
}
__device__ __forceinline__ void cpasync_mbar_arrive_noinc(uint32_t a) {
    asm volatile("cp.async.mbarrier.arrive.noinc.shared::cta.b64 [%0];" :: "r"(a) : "memory");
}
__device__ __forceinline__ void mbar_wait(uint32_t a, uint32_t parity) {
    uint32_t done;
    asm volatile("{\n\t.reg .pred p;\n\t"
                 "mbarrier.try_wait.parity.acquire.cta.shared::cta.b64 p, [%1], %2;\n\t"
                 "selp.b32 %0, 1, 0, p;\n\t}"
                 : "=r"(done) : "r"(a), "r"(parity) : "memory");
    if (!done) {
        asm volatile("{\n\t.reg .pred P1;\n\t"
                     "W_%=:\n\t"
                     "mbarrier.try_wait.parity.acquire.cta.shared::cta.b64 P1, [%0], %1, 0x989680;\n\t"
                     "@P1 bra.uni D_%=;\n\t"
                     "bra.uni W_%=;\n\t"
                     "D_%=:\n\t}"
                     :: "r"(a), "r"(parity) : "memory");
    }
}
__device__ __forceinline__ void mbar_wait_relaxed(uint32_t a, uint32_t parity) {
    uint32_t done;
    asm volatile("{\n\t.reg .pred p;\n\t"
                 "mbarrier.try_wait.parity.relaxed.cta.shared::cta.b64 p, [%1], %2;\n\t"
                 "selp.b32 %0, 1, 0, p;\n\t}"
                 : "=r"(done) : "r"(a), "r"(parity) : "memory");
    if (!done) {
        asm volatile("{\n\t.reg .pred P1;\n\t"
                     "W_%=:\n\t"
                     "mbarrier.try_wait.parity.relaxed.cta.shared::cta.b64 P1, [%0], %1, 0x989680;\n\t"
                     "@P1 bra.uni D_%=;\n\t"
                     "bra.uni W_%=;\n\t"
                     "D_%=:\n\t}"
                     :: "r"(a), "r"(parity) : "memory");
    }
}

// fragment LDS with compile-time immediate offset
#define LDS128I(v, addr, IMM) \
    asm volatile("ld.shared.v4.u32 {%0,%1,%2,%3}, [%4+%5];" \
        : "=r"((v).x), "=r"((v).y), "=r"((v).z), "=r"((v).w) \
        : "r"(addr), "n"(IMM))

#define MMA16816(acc4, A0, A1, A2, A3, B0, B1) \
    asm volatile("mma.sync.aligned.m16n8k16.row.col.f32.f16.f16.f32 " \
        "{%0,%1,%2,%3}, {%4,%5,%6,%7}, {%8,%9}, {%0,%1,%2,%3};" \
        : "+f"((acc4)[0]), "+f"((acc4)[1]), "+f"((acc4)[2]), "+f"((acc4)[3]) \
        : "r"(A0), "r"(A1), "r"(A2), "r"(A3), "r"(B0), "r"(B1))

// ---- prepass: fp32 -> fp16 with per-32-group fragment permutation ----
__global__ void prep_kernel(const float* __restrict__ x, const float* __restrict__ W,
                            int xch, int totch) {
    int t = blockIdx.x * 256 + threadIdx.x;
    if (t >= totch) return;
    const float* src;
    __half* dst;
    int ch = t;
    if (t < xch) { src = x; dst = g_x; }
    else         { src = W; dst = g_w; ch = t - xch; }
    int gb = (ch >> 2) * 32 + (ch & 3) * 2;
    __half2 h0 = __float22half2_rn(*reinterpret_cast<const float2*>(src + gb));
    __half2 h1 = __float22half2_rn(*reinterpret_cast<const float2*>(src + gb + 8));
    __half2 h2 = __float22half2_rn(*reinterpret_cast<const float2*>(src + gb + 16));
    __half2 h3 = __float22half2_rn(*reinterpret_cast<const float2*>(src + gb + 24));
    uint4 v;
    v.x = *reinterpret_cast<uint32_t*>(&h0);
    v.y = *reinterpret_cast<uint32_t*>(&h1);
    v.z = *reinterpret_cast<uint32_t*>(&h2);
    v.w = *reinterpret_cast<uint32_t*>(&h3);
    reinterpret_cast<uint4*>(dst)[ch] = v;
}

extern __shared__ char smem[];

__global__ __launch_bounds__(256, 2) void spiral_mma_kernel(
    const float* __restrict__ bias,
    const int*   __restrict__ adj,
    const float* __restrict__ zp,
    float*       __restrict__ out)
{
    const int tid = threadIdx.x;
    const int m0 = blockIdx.x * BM;
    uint32_t sb;
    asm("{ .reg .u64 t; cvta.to.shared.u64 t, %1; cvt.u32.u64 %0, t; }"
        : "=r"(sb) : "l"(smem));

    uint32_t* atab  = reinterpret_cast<uint32_t*>(smem + OFF_ATAB);
    float*    sbias = reinterpret_cast<float*>(smem + OFF_BIAS);

    for (int i = tid; i < BM * Sq; i += 256) {
        int r = i >> 4, s = i & 15;
        int mm = m0 + r;
        int b = mm / Nq, n = mm - b * Nq;
        atab[i] = (uint32_t)(b * Nq + adj[n * Sq + s]) << 8;
    }
    if (tid < OUTq) sbias[tid] = bias[tid];
    if (tid == 0) {
        #pragma unroll
        for (int s = 0; s < NST; ++s) {
            mbar_init(sb + OFF_MBAR + s * 16, 256);      // full[s]
            mbar_init(sb + OFF_MBAR + s * 16 + 8, 256);  // empty[s]
        }
    }
    __syncthreads();

    // loader: 8 lanes per 128B row; rows lr+32j
    const int lr = tid >> 3;
    const int lc = tid & 7;
    const int gsl = lc >> 2;
    const int csl = lc & 3;
    const uint32_t* atp = atab + lr * 16;
    int adst[4];
    const char* wsrc[4];
    #pragma unroll
    for (int j = 0; j < 4; ++j) {
        int row = lr + j * 32;
        int pos = ((gsl ^ (row & 1)) << 2) + (csl ^ ((row >> 1) & 3));
        adst[j] = row * 128 + (pos << 4);
        wsrc[j] = reinterpret_cast<const char*>(g_w) + row * (Kq * 2) + lc * 16;
    }

    auto produce = [&](int st, int parity, int it2) {
        mbar_wait_relaxed(sb + OFF_MBAR + st * 16 + 8, parity);   // empty[st]
        const int sidx = it2 >> 1;
        const char* gx = reinterpret_cast<const char*>(g_x)
                       + ((it2 & 1) << 7) + lc * 16;
        const int wadv = it2 << 7;
        char* abase = smem + OFF_A + st * STG;
        char* bbase = smem + OFF_B + st * STG;
        #pragma unroll
        for (int j = 0; j < 4; ++j)
            cp_async16(abase + adst[j], gx + atp[512 * j + sidx]);
        #pragma unroll
        for (int j = 0; j < 4; ++j)
            cp_async16(bbase + adst[j], wsrc[j] + wadv);
        cpasync_mbar_arrive_noinc(sb + OFF_MBAR + st * 16);       // full[st]
    };

    const int lane = tid & 31;
    const int warp = tid >> 5;
    const int wm = (warp & 1) * 64;   // 2 warps over M
    const int wn = (warp >> 1) * 32;  // 4 warps over N
    const int tr = lane >> 2;
    const int tc = lane & 3;
    const int par = tr & 1;
    const int q2  = tr >> 1;
    const int chn0 = ((0 ^ par) << 2) + (tc ^ q2);
    const int chn1 = ((1 ^ par) << 2) + (tc ^ q2);

    // fragment address bases (per-thread constants; 4 regs)
    const uint32_t abase0 = sb + OFF_A + (wm + tr) * 128 + chn0 * 16;
    const uint32_t abase1 = sb + OFF_A + (wm + tr) * 128 + chn1 * 16;
    const uint32_t bbase0 = sb + OFF_B + (wn + tr) * 128 + chn0 * 16;
    const uint32_t bbase1 = sb + OFF_B + (wn + tr) * 128 + chn1 * 16;

    float acc[4][4][4];
    #pragma unroll
    for (int a = 0; a < 4; ++a)
        #pragma unroll
        for (int b2 = 0; b2 < 4; ++b2)
            #pragma unroll
            for (int cc = 0; cc < 4; ++cc) acc[a][b2][cc] = 0.f;

    // one g-group: 4 B frags + per-mt A frags + 32 MMAs, all [reg+imm] LDS
#define CONSUME_G(AB, BB)                                                     \
    {                                                                         \
        uint4 bf0, bf1, bf2, bf3;                                             \
        LDS128I(bf0, (BB), 0);                                                \
        LDS128I(bf1, (BB), 1024);                                             \
        LDS128I(bf2, (BB), 2048);                                             \
        LDS128I(bf3, (BB), 3072);                                             \
        MT_BLOCK(0, AB) MT_BLOCK(1, AB) MT_BLOCK(2, AB) MT_BLOCK(3, AB)       \
    }
#define MT_BLOCK(MT, AB)                                                      \
    {                                                                         \
        uint4 alo, ahi;                                                       \
        LDS128I(alo, (AB), (MT)*2048);                                        \
        LDS128I(ahi, (AB), (MT)*2048 + 1024);                                 \
        MMA16816(acc[MT][0], alo.x, ahi.x, alo.y, ahi.y, bf0.x, bf0.y);       \
        MMA16816(acc[MT][1], alo.x, ahi.x, alo.y, ahi.y, bf1.x, bf1.y);       \
        MMA16816(acc[MT][2], alo.x, ahi.x, alo.y, ahi.y, bf2.x, bf2.y);       \
        MMA16816(acc[MT][3], alo.x, ahi.x, alo.y, ahi.y, bf3.x, bf3.y);       \
        MMA16816(acc[MT][0], alo.z, ahi.z, alo.w, ahi.w, bf0.z, bf0.w);       \
        MMA16816(acc[MT][1], alo.z, ahi.z, alo.w, ahi.w, bf1.z, bf1.w);       \
        MMA16816(acc[MT][2], alo.z, ahi.z, alo.w, ahi.w, bf2.z, bf2.w);       \
        MMA16816(acc[MT][3], alo.z, ahi.z, alo.w, ahi.w, bf3.z, bf3.w);       \
    }

    // prologue (fresh-barrier empty-waits pass with parity 1)
    produce(0, 1, 0);
    produce(1, 1, 1);

    int ps = 2, pp = 1;
    int cs = 0, cp = 0;
    #pragma unroll 1
    for (int it = 0; it < NITER; ++it) {
        mbar_wait(sb + OFF_MBAR + cs * 16, cp);         // full[cs] (acquire)
        const uint32_t co = (uint32_t)(cs * STG);
        const uint32_t ab0 = abase0 + co, ab1 = abase1 + co;
        const uint32_t bb0 = bbase0 + co, bb1 = bbase1 + co;

        CONSUME_G(ab0, bb0)                              // g0 MMAs

        if (it + 2 < NITER) {                            // produce under g-gap
            produce(ps, pp, it + 2);
            if (++ps == NST) { ps = 0; pp ^= 1; }
        }

        CONSUME_G(ab1, bb1)                              // g1 MMAs

        mbar_arrive(sb + OFF_MBAR + cs * 16 + 8);        // empty[cs]
        if (++cs == NST) { cs = 0; cp ^= 1; }
    }

    // ---- epilogue: bias + relu + zero_padding ----
    #pragma unroll
    for (int mt = 0; mt < 4; ++mt) {
        #pragma unroll
        for (int hh = 0; hh < 2; ++hh) {
            int m = m0 + wm + mt * 16 + hh * 8 + tr;
            float z = zp[m % Nq];
            float* orow = out + (long)m * OUTq;
            #pragma unroll
            for (int nt = 0; nt < 4; ++nt) {
                int o = wn + nt * 8 + 2 * tc;
                float v0 = fmaxf(acc[mt][nt][hh * 2 + 0] + sbias[o], 0.f) * z;
                float v1 = fmaxf(acc[mt][nt][hh * 2 + 1] + sbias[o + 1], 0.f) * z;
                *reinterpret_cast<float2*>(orow + o) = make_float2(v0, v1);
            }
        }
    }
}

extern "C" void kernel_launch(void* const* d_in, const int* in_sizes, int n_in,
                              void* d_out, int out_size) {
    const float* x    = (const float*)d_in[0];
    const float* W    = (const float*)d_in[1];
    const float* bias = (const float*)d_in[2];
    const int*   adj  = (const int*)d_in[3];
    const float* zp   = (const float*)d_in[4];
    float* out = (float*)d_out;

    int xch = (Bq * Nq * Fq) / 8;
    int totch = xch + (OUTq * Kq) / 8;
    prep_kernel<<<(totch + 255) / 256, 256>>>(x, W, xch, totch);

    cudaFuncSetAttribute(spiral_mma_kernel,
                         cudaFuncAttributeMaxDynamicSharedMemorySize, SMEM_BYTES);
    spiral_mma_kernel<<<Mtot / BM, 256, SMEM_BYTES>>>(bias, adj, zp, out);
}

// round 15
// speedup vs baseline: 1.9840x; 1.0016x over previous
#include <cuda_runtime.h>
#include <cuda_fp16.h>
#include <cstdint>

// SpiralConv gather-GEMM. R15 = R14 (FP16 m16n8k16, BK=64, mbar free-run,
// imm-offset fragment LDS) + persistent CTAs with atomic work stealing to
// kill wave quantization (750 tiles over 296 slots -> 3-wave makespan).
// out[m,o] = relu(sum_k A[m,k]*W[o,k] + b[o]) * zp[m%N]; M=96000, K=2048, N=128.

constexpr int Bq = 8, Nq = 12000, Fq = 128, Sq = 16, OUTq = 128;
constexpr int Kq = Sq * Fq;       // 2048
constexpr int Mtot = Bq * Nq;     // 96000
constexpr int BM = 128;
constexpr int NTILES = Mtot / BM; // 750
constexpr int NITER = Kq / 64;    // 32 (BK=64)
constexpr int NST = 3;

__device__ __half g_x[Bq * Nq * Fq];
__device__ __half g_w[OUTq * Kq];
__device__ unsigned g_tile_ctr;

constexpr int STG = BM * 128;                       // 16384 per tile stage
constexpr int OFF_A = 0;
constexpr int OFF_B = OFF_A + NST * STG;            // 49152
constexpr int OFF_ATAB = OFF_B + NST * STG;         // 98304
constexpr int OFF_BIAS = OFF_ATAB + BM * Sq * 4;    // 106496
constexpr int OFF_MBAR = OFF_BIAS + OUTq * 4;       // 107008
constexpr int OFF_TILE = OFF_MBAR + NST * 16;       // 107056
constexpr int SMEM_BYTES = OFF_TILE + 16;           // 107072

__device__ __forceinline__ void cp_async16(void* sdst, const void* gsrc) {
    unsigned d = (unsigned)__cvta_generic_to_shared(sdst);
    asm volatile("cp.async.cg.shared.global [%0], [%1], 16;" :: "r"(d), "l"(gsrc));
}

__device__ __forceinline__ void mbar_init(uint32_t a, uint32_t cnt) {
    asm volatile("mbarrier.init.shared.b64 [%0], %1;" :: "r"(a), "r"(cnt) : "memory");
}
__device__ __forceinline__ void mbar_arrive(uint32_t a) {
    asm volatile("mbarrier.arrive.shared::cta.b64 _, [%0];" :: "r"(a) : "memory");
}
__device__ __forceinline__ void cpasync_mbar_arrive_noinc(uint32_t a) {
    asm volatile("cp.async.mbarrier.arrive.noinc.shared::cta.b64 [%0];" :: "r"(a) : "memory");
}
__device__ __forceinline__ void mbar_wait(uint32_t a, uint32_t parity) {
    uint32_t done;
    asm volatile("{\n\t.reg .pred p;\n\t"
                 "mbarrier.try_wait.parity.acquire.cta.shared::cta.b64 p, [%1], %2;\n\t"
                 "selp.b32 %0, 1, 0, p;\n\t}"
                 : "=r"(done) : "r"(a), "r"(parity) : "memory");
    if (!done) {
        asm volatile("{\n\t.reg .pred P1;\n\t"
                     "W_%=:\n\t"
                     "mbarrier.try_wait.parity.acquire.cta.shared::cta.b64 P1, [%0], %1, 0x989680;\n\t"
                     "@P1 bra.uni D_%=;\n\t"
                     "bra.uni W_%=;\n\t"
                     "D_%=:\n\t}"
                     :: "r"(a), "r"(parity) : "memory");
    }
}
__device__ __forceinline__ void mbar_wait_relaxed(uint32_t a, uint32_t parity) {
    uint32_t done;
    asm volatile("{\n\t.reg .pred p;\n\t"
                 "mbarrier.try_wait.parity.relaxed.cta.shared::cta.b64 p, [%1], %2;\n\t"
                 "selp.b32 %0, 1, 0, p;\n\t}"
                 : "=r"(done) : "r"(a), "r"(parity) : "memory");
    if (!done) {
        asm volatile("{\n\t.reg .pred P1;\n\t"
                     "W_%=:\n\t"
                     "mbarrier.try_wait.parity.relaxed.cta.shared::cta.b64 P1, [%0], %1, 0x989680;\n\t"
                     "@P1 bra.uni D_%=;\n\t"
                     "bra.uni W_%=;\n\t"
                     "D_%=:\n\t}"
                     :: "r"(a), "r"(parity) : "memory");
    }
}

#define LDS128I(v, addr, IMM) \
    asm volatile("ld.shared.v4.u32 {%0,%1,%2,%3}, [%4+%5];" \
        : "=r"((v).x), "=r"((v).y), "=r"((v).z), "=r"((v).w) \
        : "r"(addr), "n"(IMM))

#define MMA16816(acc4, A0, A1, A2, A3, B0, B1) \
    asm volatile("mma.sync.aligned.m16n8k16.row.col.f32.f16.f16.f32 " \
        "{%0,%1,%2,%3}, {%4,%5,%6,%7}, {%8,%9}, {%0,%1,%2,%3};" \
        : "+f"((acc4)[0]), "+f"((acc4)[1]), "+f"((acc4)[2]), "+f"((acc4)[3]) \
        : "r"(A0), "r"(A1), "r"(A2), "r"(A3), "r"(B0), "r"(B1))

// ---- prepass: fp32 -> fp16 with per-32-group fragment permutation ----
__global__ void prep_kernel(const float* __restrict__ x, const float* __restrict__ W,
                            int xch, int totch) {
    int t = blockIdx.x * 256 + threadIdx.x;
    if (t == 0) g_tile_ctr = 0;       // reset work-steal counter every launch
    if (t >= totch) return;
    const float* src;
    __half* dst;
    int ch = t;
    if (t < xch) { src = x; dst = g_x; }
    else         { src = W; dst = g_w; ch = t - xch; }
    int gb = (ch >> 2) * 32 + (ch & 3) * 2;
    __half2 h0 = __float22half2_rn(*reinterpret_cast<const float2*>(src + gb));
    __half2 h1 = __float22half2_rn(*reinterpret_cast<const float2*>(src + gb + 8));
    __half2 h2 = __float22half2_rn(*reinterpret_cast<const float2*>(src + gb + 16));
    __half2 h3 = __float22half2_rn(*reinterpret_cast<const float2*>(src + gb + 24));
    uint4 v;
    v.x = *reinterpret_cast<uint32_t*>(&h0);
    v.y = *reinterpret_cast<uint32_t*>(&h1);
    v.z = *reinterpret_cast<uint32_t*>(&h2);
    v.w = *reinterpret_cast<uint32_t*>(&h3);
    reinterpret_cast<uint4*>(dst)[ch] = v;
}

extern __shared__ char smem[];

__global__ __launch_bounds__(256, 2) void spiral_mma_kernel(
    const float* __restrict__ bias,
    const int*   __restrict__ adj,
    const float* __restrict__ zp,
    float*       __restrict__ out)
{
    const int tid = threadIdx.x;
    uint32_t sb;
    asm("{ .reg .u64 t; cvta.to.shared.u64 t, %1; cvt.u32.u64 %0, t; }"
        : "=r"(sb) : "l"(smem));

    uint32_t* atab  = reinterpret_cast<uint32_t*>(smem + OFF_ATAB);
    float*    sbias = reinterpret_cast<float*>(smem + OFF_BIAS);
    volatile unsigned* tileslot = reinterpret_cast<volatile unsigned*>(smem + OFF_TILE);

    if (tid < OUTq) sbias[tid] = bias[tid];
    if (tid == 0) {
        #pragma unroll
        for (int s = 0; s < NST; ++s) {
            mbar_init(sb + OFF_MBAR + s * 16, 256);      // full[s]
            mbar_init(sb + OFF_MBAR + s * 16 + 8, 256);  // empty[s]
        }
    }

    // loader geometry (tile-independent)
    const int lr = tid >> 3;
    const int lc = tid & 7;
    const int gsl = lc >> 2;
    const int csl = lc & 3;
    const uint32_t* atp = atab + lr * 16;
    int adst[4];
    const char* wsrc[4];
    #pragma unroll
    for (int j = 0; j < 4; ++j) {
        int row = lr + j * 32;
        int pos = ((gsl ^ (row & 1)) << 2) + (csl ^ ((row >> 1) & 3));
        adst[j] = row * 128 + (pos << 4);
        wsrc[j] = reinterpret_cast<const char*>(g_w) + row * (Kq * 2) + lc * 16;
    }

    auto produce = [&](int st, int parity, int it2) {
        mbar_wait_relaxed(sb + OFF_MBAR + st * 16 + 8, parity);   // empty[st]
        const int sidx = it2 >> 1;
        const char* gx = reinterpret_cast<const char*>(g_x)
                       + ((it2 & 1) << 7) + lc * 16;
        const int wadv = it2 << 7;
        char* abase = smem + OFF_A + st * STG;
        char* bbase = smem + OFF_B + st * STG;
        #pragma unroll
        for (int j = 0; j < 4; ++j)
            cp_async16(abase + adst[j], gx + atp[512 * j + sidx]);
        #pragma unroll
        for (int j = 0; j < 4; ++j)
            cp_async16(bbase + adst[j], wsrc[j] + wadv);
        cpasync_mbar_arrive_noinc(sb + OFF_MBAR + st * 16);       // full[st]
    };

    const int lane = tid & 31;
    const int warp = tid >> 5;
    const int wm = (warp & 1) * 64;   // 2 warps over M
    const int wn = (warp >> 1) * 32;  // 4 warps over N
    const int tr = lane >> 2;
    const int tc = lane & 3;
    const int par = tr & 1;
    const int q2  = tr >> 1;
    const int chn0 = ((0 ^ par) << 2) + (tc ^ q2);
    const int chn1 = ((1 ^ par) << 2) + (tc ^ q2);

    const uint32_t abase0 = sb + OFF_A + (wm + tr) * 128 + chn0 * 16;
    const uint32_t abase1 = sb + OFF_A + (wm + tr) * 128 + chn1 * 16;
    const uint32_t bbase0 = sb + OFF_B + (wn + tr) * 128 + chn0 * 16;
    const uint32_t bbase1 = sb + OFF_B + (wn + tr) * 128 + chn1 * 16;

#define CONSUME_G(AB, BB)                                                     \
    {                                                                         \
        uint4 bf0, bf1, bf2, bf3;                                             \
        LDS128I(bf0, (BB), 0);                                                \
        LDS128I(bf1, (BB), 1024);                                             \
        LDS128I(bf2, (BB), 2048);                                             \
        LDS128I(bf3, (BB), 3072);                                             \
        MT_BLOCK(0, AB) MT_BLOCK(1, AB) MT_BLOCK(2, AB) MT_BLOCK(3, AB)       \
    }
#define MT_BLOCK(MT, AB)                                                      \
    {                                                                         \
        uint4 alo, ahi;                                                       \
        LDS128I(alo, (AB), (MT)*2048);                                        \
        LDS128I(ahi, (AB), (MT)*2048 + 1024);                                 \
        MMA16816(acc[MT][0], alo.x, ahi.x, alo.y, ahi.y, bf0.x, bf0.y);       \
        MMA16816(acc[MT][1], alo.x, ahi.x, alo.y, ahi.y, bf1.x, bf1.y);       \
        MMA16816(acc[MT][2], alo.x, ahi.x, alo.y, ahi.y, bf2.x, bf2.y);       \
        MMA16816(acc[MT][3], alo.x, ahi.x, alo.y, ahi.y, bf3.x, bf3.y);       \
        MMA16816(acc[MT][0], alo.z, ahi.z, alo.w, ahi.w, bf0.z, bf0.w);       \
        MMA16816(acc[MT][1], alo.z, ahi.z, alo.w, ahi.w, bf1.z, bf1.w);       \
        MMA16816(acc[MT][2], alo.z, ahi.z, alo.w, ahi.w, bf2.z, bf2.w);       \
        MMA16816(acc[MT][3], alo.z, ahi.z, alo.w, ahi.w, bf3.z, bf3.w);       \
    }

    // pipeline cursors persist across tiles (counts stay balanced)
    int ps = 0, pp = 1;   // producer: fresh-barrier empty-waits pass at parity 1
    int cs = 0, cp = 0;   // consumer

    #pragma unroll 1
    while (true) {
        __syncthreads();                   // prior tile epilogue + atab reads done
        if (tid == 0) *tileslot = atomicAdd(&g_tile_ctr, 1u);
        __syncthreads();
        const unsigned tile = *tileslot;
        if (tile >= (unsigned)NTILES) break;
        const int m0 = (int)tile * BM;

        // rebuild gather table for this tile
        for (int i = tid; i < BM * Sq; i += 256) {
            int r = i >> 4, s = i & 15;
            int mm = m0 + r;
            int b = mm / Nq, n = mm - b * Nq;
            atab[i] = (uint32_t)(b * Nq + adj[n * Sq + s]) << 8;
        }
        __syncthreads();

        float acc[4][4][4];
        #pragma unroll
        for (int a = 0; a < 4; ++a)
            #pragma unroll
            for (int b2 = 0; b2 < 4; ++b2)
                #pragma unroll
                for (int cc = 0; cc < 4; ++cc) acc[a][b2][cc] = 0.f;

        // tile prologue: fill 2 stages (cursor-carried)
        produce(ps, pp, 0); if (++ps == NST) { ps = 0; pp ^= 1; }
        produce(ps, pp, 1); if (++ps == NST) { ps = 0; pp ^= 1; }

        #pragma unroll 1
        for (int it = 0; it < NITER; ++it) {
            mbar_wait(sb + OFF_MBAR + cs * 16, cp);      // full[cs]
            const uint32_t co = (uint32_t)(cs * STG);
            const uint32_t ab0 = abase0 + co, ab1 = abase1 + co;
            const uint32_t bb0 = bbase0 + co, bb1 = bbase1 + co;

            CONSUME_G(ab0, bb0)

            if (it + 2 < NITER) {
                produce(ps, pp, it + 2);
                if (++ps == NST) { ps = 0; pp ^= 1; }
            }

            CONSUME_G(ab1, bb1)

            mbar_arrive(sb + OFF_MBAR + cs * 16 + 8);    // empty[cs]
            if (++cs == NST) { cs = 0; cp ^= 1; }
        }

        // ---- epilogue: bias + relu + zero_padding ----
        #pragma unroll
        for (int mt = 0; mt < 4; ++mt) {
            #pragma unroll
            for (int hh = 0; hh < 2; ++hh) {
                int m = m0 + wm + mt * 16 + hh * 8 + tr;
                float z = zp[m % Nq];
                float* orow = out + (long)m * OUTq;
                #pragma unroll
                for (int nt = 0; nt < 4; ++nt) {
                    int o = wn + nt * 8 + 2 * tc;
                    float v0 = fmaxf(acc[mt][nt][hh * 2 + 0] + sbias[o], 0.f) * z;
                    float v1 = fmaxf(acc[mt][nt][hh * 2 + 1] + sbias[o + 1], 0.f) * z;
                    *reinterpret_cast<float2*>(orow + o) = make_float2(v0, v1);
                }
            }
        }
    }
}

extern "C" void kernel_launch(void* const* d_in, const int* in_sizes, int n_in,
                              void* d_out, int out_size) {
    const float* x    = (const float*)d_in[0];
    const float* W    = (const float*)d_in[1];
    const float* bias = (const float*)d_in[2];
    const int*   adj  = (const int*)d_in[3];
    const float* zp   = (const float*)d_in[4];
    float* out = (float*)d_out;

    int xch = (Bq * Nq * Fq) / 8;
    int totch = xch + (OUTq * Kq) / 8;
    prep_kernel<<<(totch + 255) / 256, 256>>>(x, W, xch, totch);

    static int grid = 0;
    if (!grid) {
        int sms = 0;
        cudaDeviceGetAttribute(&sms, cudaDevAttrMultiProcessorCount, 0);
        grid = 2 * sms;
        if (grid > NTILES) grid = NTILES;
        cudaFuncSetAttribute(spiral_mma_kernel,
                             cudaFuncAttributeMaxDynamicSharedMemorySize, SMEM_BYTES);
    }
    spiral_mma_kernel<<<grid, 256, SMEM_BYTES>>>(bias, adj, zp, out);
}